// round 15
// baseline (speedup 1.0000x reference)
#include <cuda_runtime.h>
#include <cuda_bf16.h>
#include <cstdint>

#define Tn   4096
#define Cn   512
#define Pn   64
#define PSn  16
#define CSn  5
#define MBn  128
#define FDn  128
#define Bn   2
#define TT   64          // t-tile of res kernel
#define FT   16          // t-tile of final kernel
#define ZT   64          // t-tile of z kernel
#define ZK   16          // k-tile of z kernel

// Scratch (device globals; no allocation allowed)
__device__ __align__(16) float  g_wcomb[Cn * FDn];          // W_proj2 @ W_FINAL
__device__ __align__(16) float  g_z[Bn * Tn * FDn];         // y @ Wcomb (4 MB)
__device__ __align__(16) float4 g_yc4[Bn * Tn];             // yc[0..3] (float4 rows)
__device__ __align__(16) float  g_yc1[Bn * Tn];             // yc[4]
__device__ __align__(16) float  g_res[Bn * Tn * Pn];        // res (2 MB)

__device__ __forceinline__ unsigned long long ffma2(unsigned long long a,
                                                    unsigned long long b,
                                                    unsigned long long c) {
    unsigned long long d;
    asm("fma.rn.f32x2 %0, %1, %2, %3;" : "=l"(d) : "l"(a), "l"(b), "l"(c));
    return d;
}
__device__ __forceinline__ unsigned long long dup2(float v) {
    unsigned long long d;
    asm("mov.b64 %0, {%1, %1};" : "=l"(d) : "f"(v));
    return d;
}

// ---------------------------------------------------------------------------
// Wcomb[c][f] = sum_m W_proj2[c][m] * W_FINAL[m][f]
// ---------------------------------------------------------------------------
__global__ void wcomb_kernel(const float* __restrict__ Wp2,
                             const float* __restrict__ Wfin) {
    __shared__ float wp[4][MBn];
    const int tid = threadIdx.x;
    const int c0 = blockIdx.x * 4;
#pragma unroll
    for (int i = 0; i < 4; i++)
        wp[i][tid] = Wp2[(c0 + i) * MBn + tid];
    __syncthreads();
    float a0 = 0.f, a1 = 0.f, a2 = 0.f, a3 = 0.f;
#pragma unroll 8
    for (int m = 0; m < MBn; m++) {
        const float wf = Wfin[m * FDn + tid];
        a0 += wp[0][m] * wf; a1 += wp[1][m] * wf;
        a2 += wp[2][m] * wf; a3 += wp[3][m] * wf;
    }
    g_wcomb[(c0 + 0) * FDn + tid] = a0;
    g_wcomb[(c0 + 1) * FDn + tid] = a1;
    g_wcomb[(c0 + 2) * FDn + tid] = a2;
    g_wcomb[(c0 + 3) * FDn + tid] = a3;
}

// ---------------------------------------------------------------------------
// yc (R8 structure, MLP-fixed): 4 lanes per t-row (128 c each), shfl reduce.
// grid (Tn/32, Bn) = 256 blocks (covers all 148 SMs; old 128-block grid left
// 20 idle), 128 threads. unroll 16 -> 16 independent LDG.128 in flight.
// Writes split layout (float4 + scalar).
// ---------------------------------------------------------------------------
__global__ void __launch_bounds__(128) yc_kernel(const float* __restrict__ y,
                                                 const float* __restrict__ Wpc) {
    const int b  = blockIdx.y;
    const int tl = threadIdx.x >> 2;      // 0..31
    const int q  = threadIdx.x & 3;
    const int t  = blockIdx.x * 32 + tl;
    const float* yr = y + ((size_t)b * Tn + t) * Cn + q * 128;
    float a0 = 0.f, a1 = 0.f, a2 = 0.f, a3 = 0.f, a4 = 0.f;
#pragma unroll 16
    for (int c4 = 0; c4 < 32; c4++) {
        const float4 v = *(const float4*)(yr + c4 * 4);
        const float* w = Wpc + (q * 128 + c4 * 4) * CSn;
        a0 += v.x * __ldg(w + 0) + v.y * __ldg(w + 5) + v.z * __ldg(w + 10) + v.w * __ldg(w + 15);
        a1 += v.x * __ldg(w + 1) + v.y * __ldg(w + 6) + v.z * __ldg(w + 11) + v.w * __ldg(w + 16);
        a2 += v.x * __ldg(w + 2) + v.y * __ldg(w + 7) + v.z * __ldg(w + 12) + v.w * __ldg(w + 17);
        a3 += v.x * __ldg(w + 3) + v.y * __ldg(w + 8) + v.z * __ldg(w + 13) + v.w * __ldg(w + 18);
        a4 += v.x * __ldg(w + 4) + v.y * __ldg(w + 9) + v.z * __ldg(w + 14) + v.w * __ldg(w + 19);
    }
#pragma unroll
    for (int off = 1; off < 4; off <<= 1) {
        a0 += __shfl_xor_sync(0xFFFFFFFF, a0, off);
        a1 += __shfl_xor_sync(0xFFFFFFFF, a1, off);
        a2 += __shfl_xor_sync(0xFFFFFFFF, a2, off);
        a3 += __shfl_xor_sync(0xFFFFFFFF, a3, off);
        a4 += __shfl_xor_sync(0xFFFFFFFF, a4, off);
    }
    if (q == 0) {
        g_yc4[(size_t)b * Tn + t] = make_float4(a0, a1, a2, a3);
        g_yc1[(size_t)b * Tn + t] = a4;
    }
}

// ---------------------------------------------------------------------------
// z = y @ Wcomb, both b. Block = 64t x 128m, 256 threads, grid (64,2) = one
// wave. Thread tile 8t x 4m via fma.rn.f32x2; FMA-pipe-paced.
// ---------------------------------------------------------------------------
__global__ void __launch_bounds__(256) z_kernel(const float* __restrict__ y) {
    __shared__ __align__(16) float ws[ZK * 128];   // [k][m]  8 KB
    __shared__ __align__(16) float ys[ZK * ZT];    // [k][t]  4 KB
    const int b    = blockIdx.y;
    const int t0   = blockIdx.x * ZT;
    const int tid  = threadIdx.x;
    const int mg   = tid & 31;
    const int tg   = tid >> 5;

    unsigned long long acc[8][2];
#pragma unroll
    for (int i = 0; i < 8; i++) { acc[i][0] = 0ull; acc[i][1] = 0ull; }

    const int st = tid & 63;
    const int sk = tid >> 6;
    const float* yrow = y + ((size_t)b * Tn + t0 + st) * Cn;

    for (int c0 = 0; c0 < Cn; c0 += ZK) {
        const float4* src4 = (const float4*)(g_wcomb + c0 * 128);
#pragma unroll
        for (int i = 0; i < 2; i++)
            ((float4*)ws)[tid + i * 256] = src4[tid + i * 256];
        {
            const float4 v = *(const float4*)(yrow + c0 + sk * 4);
            ys[(sk * 4 + 0) * ZT + st] = v.x;
            ys[(sk * 4 + 1) * ZT + st] = v.y;
            ys[(sk * 4 + 2) * ZT + st] = v.z;
            ys[(sk * 4 + 3) * ZT + st] = v.w;
        }
        __syncthreads();
#pragma unroll
        for (int k = 0; k < ZK; k++) {
            const ulonglong2 wv = *(const ulonglong2*)(ws + k * 128 + mg * 4);
            const float4 ya = *(const float4*)(ys + k * ZT + tg * 8);
            const float4 yb = *(const float4*)(ys + k * ZT + tg * 8 + 4);
            const unsigned long long yd[8] = {
                dup2(ya.x), dup2(ya.y), dup2(ya.z), dup2(ya.w),
                dup2(yb.x), dup2(yb.y), dup2(yb.z), dup2(yb.w) };
#pragma unroll
            for (int i = 0; i < 8; i++) {
                acc[i][0] = ffma2(yd[i], wv.x, acc[i][0]);
                acc[i][1] = ffma2(yd[i], wv.y, acc[i][1]);
            }
        }
        __syncthreads();
    }
#pragma unroll
    for (int i = 0; i < 8; i++) {
        ulonglong2 o; o.x = acc[i][0]; o.y = acc[i][1];
        *(ulonglong2*)(g_z + ((size_t)b * Tn + t0 + tg * 8 + i) * FDn + mg * 4) = o;
    }
}

// ---------------------------------------------------------------------------
// res kernel: both b in ONE launch, grid (Tn/TT, Bn) = 128 blocks = one wave.
// 1024 threads, TT=64. Split yc table: syc4 (float4, 1 LDS.128/gather) +
// syc1 (scalar, stride-1 perfect bank spread). W_BASE transposed.
// smem: 65536 + 16384 + 20480 = 102400 B.
// ---------------------------------------------------------------------------
#define RES_SMEM_BYTES (Tn * 16 + Tn * 4 + Pn * PSn * CSn * 4)

__global__ void __launch_bounds__(1024, 1)
res_kernel(const float* __restrict__ WBASE,
           const float* __restrict__ WBIAS,
           const int*   __restrict__ patches) {
    extern __shared__ __align__(16) float sm[];
    float4* syc4 = (float4*)sm;              // [4096] float4
    float*  syc1 = (float*)(syc4 + Tn);      // [4096]
    float*  sWT  = syc1 + Tn;                // [80][64]

    const int b   = blockIdx.y;
    const int t0  = blockIdx.x * TT;
    const int tid = threadIdx.x;

    {
        const float4* s4 = g_yc4 + (size_t)b * Tn;
        const float*  s1 = g_yc1 + (size_t)b * Tn;
#pragma unroll
        for (int i = tid; i < Tn; i += 1024) {
            syc4[i] = s4[i];
            syc1[i] = s1[i];
        }
    }
    for (int i = tid; i < Pn * PSn * CSn; i += 1024) {
        const int p = i / 80;
        const int r = i % 80;
        sWT[r * 64 + p] = WBASE[i];
    }
    __syncthreads();

    const int p  = tid & 63;
    const int tl = tid >> 6;
    const float bias = __ldg(WBIAS + p);
    const float* wp = sWT + p;
#pragma unroll
    for (int c4 = 0; c4 < 4; c4++) {
        const int t = t0 + c4 * 16 + tl;
        const int4* pat = (const int4*)(patches + (size_t)t * (Pn * PSn) + p * PSn);
        const int4 i0 = __ldg(pat + 0);
        const int4 i1 = __ldg(pat + 1);
        const int4 i2 = __ldg(pat + 2);
        const int4 i3 = __ldg(pat + 3);
        const int idx[16] = { i0.x, i0.y, i0.z, i0.w,  i1.x, i1.y, i1.z, i1.w,
                              i2.x, i2.y, i2.z, i2.w,  i3.x, i3.y, i3.z, i3.w };
        float acc = 0.f;
#pragma unroll
        for (int s = 0; s < PSn; s++) {
            const float4 v  = syc4[idx[s]];
            const float  v4 = syc1[idx[s]];
            const float* w  = wp + s * (CSn * 64);
            acc += v.x * w[0] + v.y * w[64] + v.z * w[128]
                 + v.w * w[192] + v4 * w[256];
        }
        g_res[((size_t)b * Tn + t) * Pn + p] = acc + bias;
    }
}

// ---------------------------------------------------------------------------
// final kernel (mix fused): mix = res @ Wpre, then out = sum_p mix * z[pproj]
// grid (Tn/FT, Bn), 256 threads.
// ---------------------------------------------------------------------------
__global__ void __launch_bounds__(256)
final_kernel(const float* __restrict__ Wpre,
             const int*   __restrict__ pproj,
             float*       __restrict__ out) {
    __shared__ float sWpre[Pn * Pn];
    __shared__ float sres[FT * Pn];
    __shared__ float smix[FT * Pn];
    __shared__ int   spp[FT * Pn];
    const int b   = blockIdx.y;
    const int t0  = blockIdx.x * FT;
    const int tid = threadIdx.x;

    {
        const float4* wsrc = (const float4*)Wpre;
        float4* wdst = (float4*)sWpre;
#pragma unroll
        for (int i = tid; i < (Pn * Pn) / 4; i += 256) wdst[i] = wsrc[i];
        ((float4*)sres)[tid] = ((const float4*)(g_res + ((size_t)b * Tn + t0) * Pn))[tid];
        ((int4*)spp)[tid]   = ((const int4*)(pproj + (size_t)t0 * Pn))[tid];
    }
    __syncthreads();

    {
        const int q  = tid & 63;
        const int tg = tid >> 6;
        float acc[4] = {0.f, 0.f, 0.f, 0.f};
#pragma unroll 8
        for (int pp = 0; pp < Pn; pp++) {
            const float w = sWpre[pp * Pn + q];
#pragma unroll
            for (int j = 0; j < 4; j++)
                acc[j] += sres[(tg + 4 * j) * Pn + pp] * w;
        }
#pragma unroll
        for (int j = 0; j < 4; j++)
            smix[(tg + 4 * j) * Pn + q] = acc[j];
    }
    __syncthreads();

    const int lane = tid & 31;
    const int th   = tid >> 5;
    const float4* zb = (const float4*)(g_z + (size_t)b * Tn * FDn) + lane;
#pragma unroll
    for (int j = 0; j < 2; j++) {
        const int tt = th * 2 + j;
        const float* mx = smix + tt * Pn;
        const int*   pr = spp + tt * Pn;
        float4 a0 = {0,0,0,0}, a1 = {0,0,0,0}, a2 = {0,0,0,0}, a3 = {0,0,0,0};
#pragma unroll
        for (int p4 = 0; p4 < Pn; p4 += 4) {
            const float4 v0 = __ldg(zb + (size_t)pr[p4 + 0] * 32);
            const float4 v1 = __ldg(zb + (size_t)pr[p4 + 1] * 32);
            const float4 v2 = __ldg(zb + (size_t)pr[p4 + 2] * 32);
            const float4 v3 = __ldg(zb + (size_t)pr[p4 + 3] * 32);
            const float m0 = mx[p4 + 0], m1 = mx[p4 + 1];
            const float m2 = mx[p4 + 2], m3 = mx[p4 + 3];
            a0.x += m0 * v0.x; a0.y += m0 * v0.y; a0.z += m0 * v0.z; a0.w += m0 * v0.w;
            a1.x += m1 * v1.x; a1.y += m1 * v1.y; a1.z += m1 * v1.z; a1.w += m1 * v1.w;
            a2.x += m2 * v2.x; a2.y += m2 * v2.y; a2.z += m2 * v2.z; a2.w += m2 * v2.w;
            a3.x += m3 * v3.x; a3.y += m3 * v3.y; a3.z += m3 * v3.z; a3.w += m3 * v3.w;
        }
        float4 o;
        o.x = (a0.x + a1.x) + (a2.x + a3.x);
        o.y = (a0.y + a1.y) + (a2.y + a3.y);
        o.z = (a0.z + a1.z) + (a2.z + a3.z);
        o.w = (a0.w + a1.w) + (a2.w + a3.w);
        ((float4*)(out + ((size_t)b * Tn + t0 + tt) * FDn))[lane] = o;
    }
}

// ---------------------------------------------------------------------------
// Two-stream fork/join (R8 structure — best known):
//   s0: yc -> res            (smem-crossbar-bound chain)
//   s2: wcomb -> z           (FMA-bound chain)
//   join -> final on s0
// ---------------------------------------------------------------------------
static cudaStream_t g_s2 = nullptr;
static cudaEvent_t  g_evFork = nullptr, g_evJoin = nullptr;

extern "C" void kernel_launch(void* const* d_in, const int* in_sizes, int n_in,
                              void* d_out, int out_size) {
    const float* y     = (const float*)d_in[0];
    const float* WBASE = (const float*)d_in[1];
    const float* WBIAS = (const float*)d_in[2];
    const float* Wp2   = (const float*)d_in[3];
    const float* Wpc   = (const float*)d_in[4];
    const float* Wpre  = (const float*)d_in[5];
    const float* Wfin  = (const float*)d_in[6];
    const int*   patches = (const int*)d_in[7];
    const int*   pproj   = (const int*)d_in[8];
    float* out = (float*)d_out;

    if (g_s2 == nullptr) {
        cudaStreamCreateWithFlags(&g_s2, cudaStreamNonBlocking);
        cudaEventCreateWithFlags(&g_evFork, cudaEventDisableTiming);
        cudaEventCreateWithFlags(&g_evJoin, cudaEventDisableTiming);
        cudaFuncSetAttribute(res_kernel,
                             cudaFuncAttributeMaxDynamicSharedMemorySize,
                             RES_SMEM_BYTES);
    }

    // fork
    cudaEventRecord(g_evFork, 0);
    cudaStreamWaitEvent(g_s2, g_evFork, 0);

    // chain B on s2: wcomb -> z   (FMA-bound)
    wcomb_kernel<<<128, 128, 0, g_s2>>>(Wp2, Wfin);
    z_kernel<<<dim3(Tn / ZT, Bn), 256, 0, g_s2>>>(y);

    // chain A on stream 0: yc -> res   (smem-crossbar-bound)
    yc_kernel<<<dim3(Tn / 32, Bn), 128>>>(y, Wpc);
    res_kernel<<<dim3(Tn / TT, Bn), 1024, RES_SMEM_BYTES>>>(
        WBASE, WBIAS, patches);

    // join, then final
    cudaEventRecord(g_evJoin, g_s2);
    cudaStreamWaitEvent(0, g_evJoin, 0);
    final_kernel<<<dim3(Tn / FT, Bn), 256>>>(Wpre, pproj, out);
}

// round 16
// speedup vs baseline: 1.0716x; 1.0716x over previous
#include <cuda_runtime.h>
#include <cuda_bf16.h>
#include <cstdint>

#define Tn   4096
#define Cn   512
#define Pn   64
#define PSn  16
#define CSn  5
#define MBn  128
#define FDn  128
#define Bn   2
#define TT   64          // t-tile of fused res+final kernel
#define ZT   64          // t-tile of z kernel
#define ZK   16          // k-tile of z kernel

// Scratch (device globals; no allocation allowed)
__device__ __align__(16) float  g_wcomb[Cn * FDn];          // W_proj2 @ W_FINAL
__device__ __align__(16) float  g_z[Bn * Tn * FDn];         // y @ Wcomb (4 MB)
__device__ __align__(16) float4 g_yc4[Bn * Tn];             // yc[0..3] (float4 rows)
__device__ __align__(16) float  g_yc1[Bn * Tn];             // yc[4]

__device__ __forceinline__ unsigned long long ffma2(unsigned long long a,
                                                    unsigned long long b,
                                                    unsigned long long c) {
    unsigned long long d;
    asm("fma.rn.f32x2 %0, %1, %2, %3;" : "=l"(d) : "l"(a), "l"(b), "l"(c));
    return d;
}
__device__ __forceinline__ unsigned long long dup2(float v) {
    unsigned long long d;
    asm("mov.b64 %0, {%1, %1};" : "=l"(d) : "f"(v));
    return d;
}

// ---------------------------------------------------------------------------
// Wcomb[c][f] = sum_m W_proj2[c][m] * W_FINAL[m][f]
// ---------------------------------------------------------------------------
__global__ void wcomb_kernel(const float* __restrict__ Wp2,
                             const float* __restrict__ Wfin) {
    __shared__ float wp[4][MBn];
    const int tid = threadIdx.x;
    const int c0 = blockIdx.x * 4;
#pragma unroll
    for (int i = 0; i < 4; i++)
        wp[i][tid] = Wp2[(c0 + i) * MBn + tid];
    __syncthreads();
    float a0 = 0.f, a1 = 0.f, a2 = 0.f, a3 = 0.f;
#pragma unroll 8
    for (int m = 0; m < MBn; m++) {
        const float wf = Wfin[m * FDn + tid];
        a0 += wp[0][m] * wf; a1 += wp[1][m] * wf;
        a2 += wp[2][m] * wf; a3 += wp[3][m] * wf;
    }
    g_wcomb[(c0 + 0) * FDn + tid] = a0;
    g_wcomb[(c0 + 1) * FDn + tid] = a1;
    g_wcomb[(c0 + 2) * FDn + tid] = a2;
    g_wcomb[(c0 + 3) * FDn + tid] = a3;
}

// ---------------------------------------------------------------------------
// yc (R13 version — empirically best): 4 lanes per t-row (128 c each),
// shfl reduce over 4 lanes. Writes split layout (float4 + scalar).
// grid (Tn/64, Bn), 256 threads.
// ---------------------------------------------------------------------------
__global__ void __launch_bounds__(256) yc_kernel(const float* __restrict__ y,
                                                 const float* __restrict__ Wpc) {
    const int b  = blockIdx.y;
    const int tl = threadIdx.x >> 2;
    const int q  = threadIdx.x & 3;
    const int t  = blockIdx.x * 64 + tl;
    const float* yr = y + ((size_t)b * Tn + t) * Cn + q * 128;
    float a0 = 0.f, a1 = 0.f, a2 = 0.f, a3 = 0.f, a4 = 0.f;
#pragma unroll 4
    for (int c4 = 0; c4 < 32; c4++) {
        const float4 v = *(const float4*)(yr + c4 * 4);
        const float* w = Wpc + (q * 128 + c4 * 4) * CSn;
        a0 += v.x * __ldg(w + 0) + v.y * __ldg(w + 5) + v.z * __ldg(w + 10) + v.w * __ldg(w + 15);
        a1 += v.x * __ldg(w + 1) + v.y * __ldg(w + 6) + v.z * __ldg(w + 11) + v.w * __ldg(w + 16);
        a2 += v.x * __ldg(w + 2) + v.y * __ldg(w + 7) + v.z * __ldg(w + 12) + v.w * __ldg(w + 17);
        a3 += v.x * __ldg(w + 3) + v.y * __ldg(w + 8) + v.z * __ldg(w + 13) + v.w * __ldg(w + 18);
        a4 += v.x * __ldg(w + 4) + v.y * __ldg(w + 9) + v.z * __ldg(w + 14) + v.w * __ldg(w + 19);
    }
#pragma unroll
    for (int off = 1; off < 4; off <<= 1) {
        a0 += __shfl_xor_sync(0xFFFFFFFF, a0, off);
        a1 += __shfl_xor_sync(0xFFFFFFFF, a1, off);
        a2 += __shfl_xor_sync(0xFFFFFFFF, a2, off);
        a3 += __shfl_xor_sync(0xFFFFFFFF, a3, off);
        a4 += __shfl_xor_sync(0xFFFFFFFF, a4, off);
    }
    if (q == 0) {
        g_yc4[(size_t)b * Tn + t] = make_float4(a0, a1, a2, a3);
        g_yc1[(size_t)b * Tn + t] = a4;
    }
}

// ---------------------------------------------------------------------------
// z = y @ Wcomb, both b. Block = 64t x 128m, 256 threads, grid (64,2) = one
// wave. Thread tile 8t x 4m via fma.rn.f32x2; FMA-pipe-paced.
// ---------------------------------------------------------------------------
__global__ void __launch_bounds__(256) z_kernel(const float* __restrict__ y) {
    __shared__ __align__(16) float ws[ZK * 128];   // [k][m]  8 KB
    __shared__ __align__(16) float ys[ZK * ZT];    // [k][t]  4 KB
    const int b    = blockIdx.y;
    const int t0   = blockIdx.x * ZT;
    const int tid  = threadIdx.x;
    const int mg   = tid & 31;
    const int tg   = tid >> 5;

    unsigned long long acc[8][2];
#pragma unroll
    for (int i = 0; i < 8; i++) { acc[i][0] = 0ull; acc[i][1] = 0ull; }

    const int st = tid & 63;
    const int sk = tid >> 6;
    const float* yrow = y + ((size_t)b * Tn + t0 + st) * Cn;

    for (int c0 = 0; c0 < Cn; c0 += ZK) {
        const float4* src4 = (const float4*)(g_wcomb + c0 * 128);
#pragma unroll
        for (int i = 0; i < 2; i++)
            ((float4*)ws)[tid + i * 256] = src4[tid + i * 256];
        {
            const float4 v = *(const float4*)(yrow + c0 + sk * 4);
            ys[(sk * 4 + 0) * ZT + st] = v.x;
            ys[(sk * 4 + 1) * ZT + st] = v.y;
            ys[(sk * 4 + 2) * ZT + st] = v.z;
            ys[(sk * 4 + 3) * ZT + st] = v.w;
        }
        __syncthreads();
#pragma unroll
        for (int k = 0; k < ZK; k++) {
            const ulonglong2 wv = *(const ulonglong2*)(ws + k * 128 + mg * 4);
            const float4 ya = *(const float4*)(ys + k * ZT + tg * 8);
            const float4 yb = *(const float4*)(ys + k * ZT + tg * 8 + 4);
            const unsigned long long yd[8] = {
                dup2(ya.x), dup2(ya.y), dup2(ya.z), dup2(ya.w),
                dup2(yb.x), dup2(yb.y), dup2(yb.z), dup2(yb.w) };
#pragma unroll
            for (int i = 0; i < 8; i++) {
                acc[i][0] = ffma2(yd[i], wv.x, acc[i][0]);
                acc[i][1] = ffma2(yd[i], wv.y, acc[i][1]);
            }
        }
        __syncthreads();
    }
#pragma unroll
    for (int i = 0; i < 8; i++) {
        ulonglong2 o; o.x = acc[i][0]; o.y = acc[i][1];
        *(ulonglong2*)(g_z + ((size_t)b * Tn + t0 + tg * 8 + i) * FDn + mg * 4) = o;
    }
}

// ---------------------------------------------------------------------------
// FUSED res + mix + final: one kernel, grid (Tn/TT, Bn) = 128 blocks,
// 1024 threads, 1 CTA/SM. Phases:
//   1. res:   gathers from split yc tables in smem (R13-proven layout)
//   2. mix:   sres @ Wpre -> smix  (all in smem)
//   3. final: out[t,f] = sum_p smix[t][p] * z[pproj[t][p]][f]  (coalesced
//             float4 z-row gathers, warp per 2 t-rows)
// Eliminates g_res roundtrip (4 MB), the final launch, and one join.
// smem: syc4 64K | syc1 16K | sWT 20K | sWpre 16K | sres 16K | smix 16K |
//       spp 16K = 164 KB.
// ---------------------------------------------------------------------------
#define RESF_SMEM_BYTES (Tn*16 + Tn*4 + Pn*PSn*CSn*4 + Pn*Pn*4 + 3*TT*Pn*4)

__global__ void __launch_bounds__(1024, 1)
resfinal_kernel(const float* __restrict__ WBASE,
                const float* __restrict__ WBIAS,
                const float* __restrict__ Wpre,
                const int*   __restrict__ patches,
                const int*   __restrict__ pproj,
                float*       __restrict__ out) {
    extern __shared__ __align__(16) float sm[];
    float4* syc4  = (float4*)sm;                  // [4096] float4
    float*  syc1  = (float*)(syc4 + Tn);          // [4096]
    float*  sWT   = syc1 + Tn;                    // [80][64]
    float*  sWpre = sWT + Pn * PSn * CSn;         // [64][64]
    float*  sres  = sWpre + Pn * Pn;              // [64][64]
    float*  smix  = sres + TT * Pn;               // [64][64]
    int*    spp   = (int*)(smix + TT * Pn);       // [64][64]

    const int b   = blockIdx.y;
    const int t0  = blockIdx.x * TT;
    const int tid = threadIdx.x;

    // ---- stage tables ----
    {
        const float4* s4 = g_yc4 + (size_t)b * Tn;
        const float*  s1 = g_yc1 + (size_t)b * Tn;
#pragma unroll
        for (int i = tid; i < Tn; i += 1024) {
            syc4[i] = s4[i];
            syc1[i] = s1[i];
        }
    }
    for (int i = tid; i < Pn * PSn * CSn; i += 1024) {
        const int p = i / 80;
        const int r = i % 80;
        sWT[r * 64 + p] = WBASE[i];
    }
    if (tid < (Pn * Pn) / 4)
        ((float4*)sWpre)[tid] = ((const float4*)Wpre)[tid];
    ((int4*)spp)[tid] = ((const int4*)(pproj + (size_t)t0 * Pn))[tid];
    __syncthreads();

    // ---- phase 1: res ----
    const int p  = tid & 63;
    const int tl = tid >> 6;
    const float bias = __ldg(WBIAS + p);
    const float* wp = sWT + p;
#pragma unroll
    for (int c4 = 0; c4 < 4; c4++) {
        const int t = t0 + c4 * 16 + tl;
        const int4* pat = (const int4*)(patches + (size_t)t * (Pn * PSn) + p * PSn);
        const int4 i0 = __ldg(pat + 0);
        const int4 i1 = __ldg(pat + 1);
        const int4 i2 = __ldg(pat + 2);
        const int4 i3 = __ldg(pat + 3);
        const int idx[16] = { i0.x, i0.y, i0.z, i0.w,  i1.x, i1.y, i1.z, i1.w,
                              i2.x, i2.y, i2.z, i2.w,  i3.x, i3.y, i3.z, i3.w };
        float acc = 0.f;
#pragma unroll
        for (int s = 0; s < PSn; s++) {
            const float4 v  = syc4[idx[s]];
            const float  v4 = syc1[idx[s]];
            const float* w  = wp + s * (CSn * 64);
            acc += v.x * w[0] + v.y * w[64] + v.z * w[128]
                 + v.w * w[192] + v4 * w[256];
        }
        sres[(c4 * 16 + tl) * Pn + p] = acc + bias;
    }
    __syncthreads();

    // ---- phase 2: mix (q = tid&63, tg = tid>>6 handles t in {tg + 16j}) ----
    {
        const int q  = tid & 63;
        const int tg = tid >> 6;
        float acc[4] = {0.f, 0.f, 0.f, 0.f};
#pragma unroll 8
        for (int pp = 0; pp < Pn; pp++) {
            const float w = sWpre[pp * Pn + q];
#pragma unroll
            for (int j = 0; j < 4; j++)
                acc[j] += sres[(tg + 16 * j) * Pn + pp] * w;
        }
#pragma unroll
        for (int j = 0; j < 4; j++)
            smix[(tg + 16 * j) * Pn + q] = acc[j];
    }
    __syncthreads();

    // ---- phase 3: final (warp per 2 t-rows, coalesced float4 z gathers) ----
    {
        const int lane = tid & 31;
        const int warp = tid >> 5;               // 0..31
        const float4* zb = (const float4*)(g_z + (size_t)b * Tn * FDn) + lane;
#pragma unroll
        for (int j = 0; j < 2; j++) {
            const int tt = warp * 2 + j;
            const float* mx = smix + tt * Pn;
            const int*   pr = spp + tt * Pn;
            float4 a0 = {0,0,0,0}, a1 = {0,0,0,0}, a2 = {0,0,0,0}, a3 = {0,0,0,0};
#pragma unroll
            for (int p4 = 0; p4 < Pn; p4 += 4) {
                const float4 v0 = __ldg(zb + (size_t)pr[p4 + 0] * 32);
                const float4 v1 = __ldg(zb + (size_t)pr[p4 + 1] * 32);
                const float4 v2 = __ldg(zb + (size_t)pr[p4 + 2] * 32);
                const float4 v3 = __ldg(zb + (size_t)pr[p4 + 3] * 32);
                const float m0 = mx[p4 + 0], m1 = mx[p4 + 1];
                const float m2 = mx[p4 + 2], m3 = mx[p4 + 3];
                a0.x += m0 * v0.x; a0.y += m0 * v0.y; a0.z += m0 * v0.z; a0.w += m0 * v0.w;
                a1.x += m1 * v1.x; a1.y += m1 * v1.y; a1.z += m1 * v1.z; a1.w += m1 * v1.w;
                a2.x += m2 * v2.x; a2.y += m2 * v2.y; a2.z += m2 * v2.z; a2.w += m2 * v2.w;
                a3.x += m3 * v3.x; a3.y += m3 * v3.y; a3.z += m3 * v3.z; a3.w += m3 * v3.w;
            }
            float4 o;
            o.x = (a0.x + a1.x) + (a2.x + a3.x);
            o.y = (a0.y + a1.y) + (a2.y + a3.y);
            o.z = (a0.z + a1.z) + (a2.z + a3.z);
            o.w = (a0.w + a1.w) + (a2.w + a3.w);
            ((float4*)(out + ((size_t)b * Tn + t0 + tt) * FDn))[lane] = o;
        }
    }
}

// ---------------------------------------------------------------------------
// Schedule:
//   s2: wcomb -> z -> eZ           (FMA-bound chain)
//   s0: yc -> [wait eZ] -> resfinal (crossbar/L2-bound fused kernel, writes out)
// ---------------------------------------------------------------------------
static cudaStream_t g_s2 = nullptr;
static cudaEvent_t  g_evFork = nullptr, g_evZ = nullptr;

extern "C" void kernel_launch(void* const* d_in, const int* in_sizes, int n_in,
                              void* d_out, int out_size) {
    const float* y     = (const float*)d_in[0];
    const float* WBASE = (const float*)d_in[1];
    const float* WBIAS = (const float*)d_in[2];
    const float* Wp2   = (const float*)d_in[3];
    const float* Wpc   = (const float*)d_in[4];
    const float* Wpre  = (const float*)d_in[5];
    const float* Wfin  = (const float*)d_in[6];
    const int*   patches = (const int*)d_in[7];
    const int*   pproj   = (const int*)d_in[8];
    float* out = (float*)d_out;

    if (g_s2 == nullptr) {
        cudaStreamCreateWithFlags(&g_s2, cudaStreamNonBlocking);
        cudaEventCreateWithFlags(&g_evFork, cudaEventDisableTiming);
        cudaEventCreateWithFlags(&g_evZ, cudaEventDisableTiming);
        cudaFuncSetAttribute(resfinal_kernel,
                             cudaFuncAttributeMaxDynamicSharedMemorySize,
                             RESF_SMEM_BYTES);
    }

    // fork
    cudaEventRecord(g_evFork, 0);
    cudaStreamWaitEvent(g_s2, g_evFork, 0);

    // chain B on s2: wcomb -> z   (FMA-bound)
    wcomb_kernel<<<128, 128, 0, g_s2>>>(Wp2, Wfin);
    z_kernel<<<dim3(Tn / ZT, Bn), 256, 0, g_s2>>>(y);
    cudaEventRecord(g_evZ, g_s2);

    // chain A on stream 0: yc -> [z ready] -> fused res+mix+final
    yc_kernel<<<dim3(Tn / 64, Bn), 256>>>(y, Wpc);
    cudaStreamWaitEvent(0, g_evZ, 0);
    resfinal_kernel<<<dim3(Tn / TT, Bn), 1024, RESF_SMEM_BYTES>>>(
        WBASE, WBIAS, Wpre, patches, pproj, out);
}

// round 17
// speedup vs baseline: 1.0793x; 1.0072x over previous
#include <cuda_runtime.h>
#include <cuda_bf16.h>
#include <cuda_fp16.h>
#include <cstdint>

#define Tn   4096
#define Cn   512
#define Pn   64
#define PSn  16
#define CSn  5
#define MBn  128
#define FDn  128
#define Bn   2
#define TT   64          // t-tile of fused res+final kernel
#define ZT   64          // t-tile of z kernel
#define ZK   16          // k-tile of z kernel

// Scratch (device globals; no allocation allowed)
__device__ __align__(16) float  g_wcomb[Cn * FDn];          // W_proj2 @ W_FINAL
__device__ __align__(16) __half g_zh[Bn * Tn * FDn];        // y @ Wcomb, fp16 (2 MB)
__device__ __align__(16) float4 g_yc4[Bn * Tn];             // yc[0..3] (float4 rows)
__device__ __align__(16) float  g_yc1[Bn * Tn];             // yc[4]

__device__ __forceinline__ unsigned long long ffma2(unsigned long long a,
                                                    unsigned long long b,
                                                    unsigned long long c) {
    unsigned long long d;
    asm("fma.rn.f32x2 %0, %1, %2, %3;" : "=l"(d) : "l"(a), "l"(b), "l"(c));
    return d;
}
__device__ __forceinline__ unsigned long long dup2(float v) {
    unsigned long long d;
    asm("mov.b64 %0, {%1, %1};" : "=l"(d) : "f"(v));
    return d;
}

// ---------------------------------------------------------------------------
// Wcomb[c][f] = sum_m W_proj2[c][m] * W_FINAL[m][f]
// ---------------------------------------------------------------------------
__global__ void wcomb_kernel(const float* __restrict__ Wp2,
                             const float* __restrict__ Wfin) {
    __shared__ float wp[4][MBn];
    const int tid = threadIdx.x;
    const int c0 = blockIdx.x * 4;
#pragma unroll
    for (int i = 0; i < 4; i++)
        wp[i][tid] = Wp2[(c0 + i) * MBn + tid];
    __syncthreads();
    float a0 = 0.f, a1 = 0.f, a2 = 0.f, a3 = 0.f;
#pragma unroll 8
    for (int m = 0; m < MBn; m++) {
        const float wf = Wfin[m * FDn + tid];
        a0 += wp[0][m] * wf; a1 += wp[1][m] * wf;
        a2 += wp[2][m] * wf; a3 += wp[3][m] * wf;
    }
    g_wcomb[(c0 + 0) * FDn + tid] = a0;
    g_wcomb[(c0 + 1) * FDn + tid] = a1;
    g_wcomb[(c0 + 2) * FDn + tid] = a2;
    g_wcomb[(c0 + 3) * FDn + tid] = a3;
}

// ---------------------------------------------------------------------------
// yc (R13 version — empirically best): 4 lanes per t-row (128 c each),
// shfl reduce over 4 lanes. Writes split layout (float4 + scalar).
// grid (Tn/64, Bn), 256 threads.
// ---------------------------------------------------------------------------
__global__ void __launch_bounds__(256) yc_kernel(const float* __restrict__ y,
                                                 const float* __restrict__ Wpc) {
    const int b  = blockIdx.y;
    const int tl = threadIdx.x >> 2;
    const int q  = threadIdx.x & 3;
    const int t  = blockIdx.x * 64 + tl;
    const float* yr = y + ((size_t)b * Tn + t) * Cn + q * 128;
    float a0 = 0.f, a1 = 0.f, a2 = 0.f, a3 = 0.f, a4 = 0.f;
#pragma unroll 4
    for (int c4 = 0; c4 < 32; c4++) {
        const float4 v = *(const float4*)(yr + c4 * 4);
        const float* w = Wpc + (q * 128 + c4 * 4) * CSn;
        a0 += v.x * __ldg(w + 0) + v.y * __ldg(w + 5) + v.z * __ldg(w + 10) + v.w * __ldg(w + 15);
        a1 += v.x * __ldg(w + 1) + v.y * __ldg(w + 6) + v.z * __ldg(w + 11) + v.w * __ldg(w + 16);
        a2 += v.x * __ldg(w + 2) + v.y * __ldg(w + 7) + v.z * __ldg(w + 12) + v.w * __ldg(w + 17);
        a3 += v.x * __ldg(w + 3) + v.y * __ldg(w + 8) + v.z * __ldg(w + 13) + v.w * __ldg(w + 18);
        a4 += v.x * __ldg(w + 4) + v.y * __ldg(w + 9) + v.z * __ldg(w + 14) + v.w * __ldg(w + 19);
    }
#pragma unroll
    for (int off = 1; off < 4; off <<= 1) {
        a0 += __shfl_xor_sync(0xFFFFFFFF, a0, off);
        a1 += __shfl_xor_sync(0xFFFFFFFF, a1, off);
        a2 += __shfl_xor_sync(0xFFFFFFFF, a2, off);
        a3 += __shfl_xor_sync(0xFFFFFFFF, a3, off);
        a4 += __shfl_xor_sync(0xFFFFFFFF, a4, off);
    }
    if (q == 0) {
        g_yc4[(size_t)b * Tn + t] = make_float4(a0, a1, a2, a3);
        g_yc1[(size_t)b * Tn + t] = a4;
    }
}

// ---------------------------------------------------------------------------
// z = y @ Wcomb, both b. Block = 64t x 128m, 256 threads, grid (64,2) = one
// wave. Thread tile 8t x 4m via fma.rn.f32x2; FMA-pipe-paced.
// Epilogue packs fp32 accumulators to fp16 (halves final-gather L2 traffic).
// ---------------------------------------------------------------------------
__global__ void __launch_bounds__(256) z_kernel(const float* __restrict__ y) {
    __shared__ __align__(16) float ws[ZK * 128];   // [k][m]  8 KB
    __shared__ __align__(16) float ys[ZK * ZT];    // [k][t]  4 KB
    const int b    = blockIdx.y;
    const int t0   = blockIdx.x * ZT;
    const int tid  = threadIdx.x;
    const int mg   = tid & 31;
    const int tg   = tid >> 5;

    unsigned long long acc[8][2];
#pragma unroll
    for (int i = 0; i < 8; i++) { acc[i][0] = 0ull; acc[i][1] = 0ull; }

    const int st = tid & 63;
    const int sk = tid >> 6;
    const float* yrow = y + ((size_t)b * Tn + t0 + st) * Cn;

    for (int c0 = 0; c0 < Cn; c0 += ZK) {
        const float4* src4 = (const float4*)(g_wcomb + c0 * 128);
#pragma unroll
        for (int i = 0; i < 2; i++)
            ((float4*)ws)[tid + i * 256] = src4[tid + i * 256];
        {
            const float4 v = *(const float4*)(yrow + c0 + sk * 4);
            ys[(sk * 4 + 0) * ZT + st] = v.x;
            ys[(sk * 4 + 1) * ZT + st] = v.y;
            ys[(sk * 4 + 2) * ZT + st] = v.z;
            ys[(sk * 4 + 3) * ZT + st] = v.w;
        }
        __syncthreads();
#pragma unroll
        for (int k = 0; k < ZK; k++) {
            const ulonglong2 wv = *(const ulonglong2*)(ws + k * 128 + mg * 4);
            const float4 ya = *(const float4*)(ys + k * ZT + tg * 8);
            const float4 yb = *(const float4*)(ys + k * ZT + tg * 8 + 4);
            const unsigned long long yd[8] = {
                dup2(ya.x), dup2(ya.y), dup2(ya.z), dup2(ya.w),
                dup2(yb.x), dup2(yb.y), dup2(yb.z), dup2(yb.w) };
#pragma unroll
            for (int i = 0; i < 8; i++) {
                acc[i][0] = ffma2(yd[i], wv.x, acc[i][0]);
                acc[i][1] = ffma2(yd[i], wv.y, acc[i][1]);
            }
        }
        __syncthreads();
    }
#pragma unroll
    for (int i = 0; i < 8; i++) {
        const float2 p0 = *(const float2*)&acc[i][0];   // f[mg*4+0], f[mg*4+1]
        const float2 p1 = *(const float2*)&acc[i][1];   // f[mg*4+2], f[mg*4+3]
        const __half2 h0 = __floats2half2_rn(p0.x, p0.y);
        const __half2 h1 = __floats2half2_rn(p1.x, p1.y);
        uint2 o;
        o.x = *(const unsigned int*)&h0;
        o.y = *(const unsigned int*)&h1;
        *(uint2*)(g_zh + ((size_t)b * Tn + t0 + tg * 8 + i) * FDn + mg * 4) = o;
    }
}

// ---------------------------------------------------------------------------
// FUSED res + mix + final: grid (Tn/TT, Bn) = 128 blocks, 1024 threads.
// Phase 3 gathers fp16 z rows (256 B each, half the L2 traffic of fp32).
// smem: syc4 64K | syc1 16K | sWT 20K | sWpre 16K | sres 16K | smix 16K |
//       spp 16K = 164 KB.
// ---------------------------------------------------------------------------
#define RESF_SMEM_BYTES (Tn*16 + Tn*4 + Pn*PSn*CSn*4 + Pn*Pn*4 + 3*TT*Pn*4)

__global__ void __launch_bounds__(1024, 1)
resfinal_kernel(const float* __restrict__ WBASE,
                const float* __restrict__ WBIAS,
                const float* __restrict__ Wpre,
                const int*   __restrict__ patches,
                const int*   __restrict__ pproj,
                float*       __restrict__ out) {
    extern __shared__ __align__(16) float sm[];
    float4* syc4  = (float4*)sm;                  // [4096] float4
    float*  syc1  = (float*)(syc4 + Tn);          // [4096]
    float*  sWT   = syc1 + Tn;                    // [80][64]
    float*  sWpre = sWT + Pn * PSn * CSn;         // [64][64]
    float*  sres  = sWpre + Pn * Pn;              // [64][64]
    float*  smix  = sres + TT * Pn;               // [64][64]
    int*    spp   = (int*)(smix + TT * Pn);       // [64][64]

    const int b   = blockIdx.y;
    const int t0  = blockIdx.x * TT;
    const int tid = threadIdx.x;

    // ---- stage tables ----
    {
        const float4* s4 = g_yc4 + (size_t)b * Tn;
        const float*  s1 = g_yc1 + (size_t)b * Tn;
#pragma unroll
        for (int i = tid; i < Tn; i += 1024) {
            syc4[i] = s4[i];
            syc1[i] = s1[i];
        }
    }
    for (int i = tid; i < Pn * PSn * CSn; i += 1024) {
        const int p = i / 80;
        const int r = i % 80;
        sWT[r * 64 + p] = WBASE[i];
    }
    if (tid < (Pn * Pn) / 4)
        ((float4*)sWpre)[tid] = ((const float4*)Wpre)[tid];
    ((int4*)spp)[tid] = ((const int4*)(pproj + (size_t)t0 * Pn))[tid];
    __syncthreads();

    // ---- phase 1: res ----
    const int p  = tid & 63;
    const int tl = tid >> 6;
    const float bias = __ldg(WBIAS + p);
    const float* wp = sWT + p;
#pragma unroll
    for (int c4 = 0; c4 < 4; c4++) {
        const int t = t0 + c4 * 16 + tl;
        const int4* pat = (const int4*)(patches + (size_t)t * (Pn * PSn) + p * PSn);
        const int4 i0 = __ldg(pat + 0);
        const int4 i1 = __ldg(pat + 1);
        const int4 i2 = __ldg(pat + 2);
        const int4 i3 = __ldg(pat + 3);
        const int idx[16] = { i0.x, i0.y, i0.z, i0.w,  i1.x, i1.y, i1.z, i1.w,
                              i2.x, i2.y, i2.z, i2.w,  i3.x, i3.y, i3.z, i3.w };
        float acc = 0.f;
#pragma unroll
        for (int s = 0; s < PSn; s++) {
            const float4 v  = syc4[idx[s]];
            const float  v4 = syc1[idx[s]];
            const float* w  = wp + s * (CSn * 64);
            acc += v.x * w[0] + v.y * w[64] + v.z * w[128]
                 + v.w * w[192] + v4 * w[256];
        }
        sres[(c4 * 16 + tl) * Pn + p] = acc + bias;
    }
    __syncthreads();

    // ---- phase 2: mix ----
    {
        const int q  = tid & 63;
        const int tg = tid >> 6;
        float acc[4] = {0.f, 0.f, 0.f, 0.f};
#pragma unroll 8
        for (int pp = 0; pp < Pn; pp++) {
            const float w = sWpre[pp * Pn + q];
#pragma unroll
            for (int j = 0; j < 4; j++)
                acc[j] += sres[(tg + 16 * j) * Pn + pp] * w;
        }
#pragma unroll
        for (int j = 0; j < 4; j++)
            smix[(tg + 16 * j) * Pn + q] = acc[j];
    }
    __syncthreads();

    // ---- phase 3: final (warp per 2 t-rows, fp16 z gathers: 8 B/lane/row) ----
    {
        const int lane = tid & 31;
        const int warp = tid >> 5;               // 0..31
        const uint2* zb = (const uint2*)(g_zh + (size_t)b * Tn * FDn) + lane;
#pragma unroll
        for (int j = 0; j < 2; j++) {
            const int tt = warp * 2 + j;
            const float* mx = smix + tt * Pn;
            const int*   pr = spp + tt * Pn;
            float4 a0 = {0,0,0,0}, a1 = {0,0,0,0}, a2 = {0,0,0,0}, a3 = {0,0,0,0};
#pragma unroll
            for (int p4 = 0; p4 < Pn; p4 += 4) {
                const uint2 u0 = __ldg(zb + (size_t)pr[p4 + 0] * 32);
                const uint2 u1 = __ldg(zb + (size_t)pr[p4 + 1] * 32);
                const uint2 u2 = __ldg(zb + (size_t)pr[p4 + 2] * 32);
                const uint2 u3 = __ldg(zb + (size_t)pr[p4 + 3] * 32);
                const float m0 = mx[p4 + 0], m1 = mx[p4 + 1];
                const float m2 = mx[p4 + 2], m3 = mx[p4 + 3];
                const float2 f00 = __half22float2(*(const __half2*)&u0.x);
                const float2 f01 = __half22float2(*(const __half2*)&u0.y);
                const float2 f10 = __half22float2(*(const __half2*)&u1.x);
                const float2 f11 = __half22float2(*(const __half2*)&u1.y);
                const float2 f20 = __half22float2(*(const __half2*)&u2.x);
                const float2 f21 = __half22float2(*(const __half2*)&u2.y);
                const float2 f30 = __half22float2(*(const __half2*)&u3.x);
                const float2 f31 = __half22float2(*(const __half2*)&u3.y);
                a0.x += m0 * f00.x; a0.y += m0 * f00.y; a0.z += m0 * f01.x; a0.w += m0 * f01.y;
                a1.x += m1 * f10.x; a1.y += m1 * f10.y; a1.z += m1 * f11.x; a1.w += m1 * f11.y;
                a2.x += m2 * f20.x; a2.y += m2 * f20.y; a2.z += m2 * f21.x; a2.w += m2 * f21.y;
                a3.x += m3 * f30.x; a3.y += m3 * f30.y; a3.z += m3 * f31.x; a3.w += m3 * f31.y;
            }
            float4 o;
            o.x = (a0.x + a1.x) + (a2.x + a3.x);
            o.y = (a0.y + a1.y) + (a2.y + a3.y);
            o.z = (a0.z + a1.z) + (a2.z + a3.z);
            o.w = (a0.w + a1.w) + (a2.w + a3.w);
            ((float4*)(out + ((size_t)b * Tn + t0 + tt) * FDn))[lane] = o;
        }
    }
}

// ---------------------------------------------------------------------------
// Schedule:
//   s2: wcomb -> z -> eZ           (FMA-bound chain)
//   s0: yc -> [wait eZ] -> resfinal (crossbar/L2-bound fused kernel)
// ---------------------------------------------------------------------------
static cudaStream_t g_s2 = nullptr;
static cudaEvent_t  g_evFork = nullptr, g_evZ = nullptr;

extern "C" void kernel_launch(void* const* d_in, const int* in_sizes, int n_in,
                              void* d_out, int out_size) {
    const float* y     = (const float*)d_in[0];
    const float* WBASE = (const float*)d_in[1];
    const float* WBIAS = (const float*)d_in[2];
    const float* Wp2   = (const float*)d_in[3];
    const float* Wpc   = (const float*)d_in[4];
    const float* Wpre  = (const float*)d_in[5];
    const float* Wfin  = (const float*)d_in[6];
    const int*   patches = (const int*)d_in[7];
    const int*   pproj   = (const int*)d_in[8];
    float* out = (float*)d_out;

    if (g_s2 == nullptr) {
        cudaStreamCreateWithFlags(&g_s2, cudaStreamNonBlocking);
        cudaEventCreateWithFlags(&g_evFork, cudaEventDisableTiming);
        cudaEventCreateWithFlags(&g_evZ, cudaEventDisableTiming);
        cudaFuncSetAttribute(resfinal_kernel,
                             cudaFuncAttributeMaxDynamicSharedMemorySize,
                             RESF_SMEM_BYTES);
    }

    // fork
    cudaEventRecord(g_evFork, 0);
    cudaStreamWaitEvent(g_s2, g_evFork, 0);

    // chain B on s2: wcomb -> z   (FMA-bound)
    wcomb_kernel<<<128, 128, 0, g_s2>>>(Wp2, Wfin);
    z_kernel<<<dim3(Tn / ZT, Bn), 256, 0, g_s2>>>(y);
    cudaEventRecord(g_evZ, g_s2);

    // chain A on stream 0: yc -> [z ready] -> fused res+mix+final
    yc_kernel<<<dim3(Tn / 64, Bn), 256>>>(y, Wpc);
    cudaStreamWaitEvent(0, g_evZ, 0);
    resfinal_kernel<<<dim3(Tn / TT, Bn), 1024, RESF_SMEM_BYTES>>>(
        WBASE, WBIAS, Wpre, patches, pproj, out);
}